// round 1
// baseline (speedup 1.0000x reference)
#include <cuda_runtime.h>
#include <math.h>

#define S_LEN   4096
#define DMODEL  768
#define NHEAD   12
#define HDIM    64

// Scratch (allocation-free per harness rules): head-major projected tensors + attention output.
__device__ float g_qh[NHEAD * S_LEN * HDIM];   // [H][S][Hd]
__device__ float g_kh[NHEAD * S_LEN * HDIM];
__device__ float g_vh[NHEAD * S_LEN * HDIM];
__device__ float g_attn[S_LEN * DMODEL];       // [S][H*Hd]

// ---------------------------------------------------------------------------
// GEMM: C = A(4096x768) @ W^T(768x768) + bias
// headMajor=1: C[(n>>6)][m][(n&63)]  (head-major scratch)
// headMajor=0: C[m][n]               (row-major)
// 128x128 block tile, BK=8, 8x8 per-thread microtile, 256 threads.
// ---------------------------------------------------------------------------
__global__ __launch_bounds__(256, 2)
void gemm_bias_kernel(const float* __restrict__ A, const float* __restrict__ W,
                      const float* __restrict__ bias, float* __restrict__ C,
                      int headMajor) {
    const int K = DMODEL;
    __shared__ float As[8][128];
    __shared__ float Bs[8][128];

    const int tid = threadIdx.x;
    const int m0 = blockIdx.y * 128;
    const int n0 = blockIdx.x * 128;
    const int lr = tid >> 1;          // 0..127 : tile row for loads
    const int lc = (tid & 1) * 4;     // 0 or 4 : k-subcolumn for float4 load
    const int ty = tid >> 4;          // 0..15
    const int tx = tid & 15;          // 0..15

    float acc[8][8];
#pragma unroll
    for (int i = 0; i < 8; i++)
#pragma unroll
        for (int j = 0; j < 8; j++) acc[i][j] = 0.0f;

    const float* aptr = A + (size_t)(m0 + lr) * K + lc;
    const float* bptr = W + (size_t)(n0 + lr) * K + lc;

    for (int k0 = 0; k0 < K; k0 += 8) {
        float4 av = *(const float4*)(aptr + k0);
        float4 bv = *(const float4*)(bptr + k0);
        __syncthreads();
        As[lc + 0][lr] = av.x; As[lc + 1][lr] = av.y;
        As[lc + 2][lr] = av.z; As[lc + 3][lr] = av.w;
        Bs[lc + 0][lr] = bv.x; Bs[lc + 1][lr] = bv.y;
        Bs[lc + 2][lr] = bv.z; Bs[lc + 3][lr] = bv.w;
        __syncthreads();

#pragma unroll
        for (int kk = 0; kk < 8; kk++) {
            float a[8], b[8];
#pragma unroll
            for (int i = 0; i < 8; i++) a[i] = As[kk][ty * 8 + i];
#pragma unroll
            for (int j = 0; j < 8; j++) b[j] = Bs[kk][tx * 8 + j];
#pragma unroll
            for (int i = 0; i < 8; i++)
#pragma unroll
                for (int j = 0; j < 8; j++)
                    acc[i][j] = fmaf(a[i], b[j], acc[i][j]);
        }
    }

#pragma unroll
    for (int i = 0; i < 8; i++) {
        const int m = m0 + ty * 8 + i;
#pragma unroll
        for (int j = 0; j < 8; j++) {
            const int n = n0 + tx * 8 + j;
            const float v = acc[i][j] + bias[n];
            if (headMajor)
                C[((size_t)(n >> 6) * S_LEN + m) * HDIM + (n & 63)] = v;
            else
                C[(size_t)m * DMODEL + n] = v;
        }
    }
}

// ---------------------------------------------------------------------------
// Flash attention, fp32. Block = (head, 64-row Q tile). 256 threads = 8 warps.
// Warp w owns query rows w*8..w*8+7; lane owns score/output cols {2*lane, 2*lane+1}.
// K staged d-major in smem (conflict-free float2 loads along t).
// ---------------------------------------------------------------------------
__global__ __launch_bounds__(256, 2)
void attn_kernel() {
    extern __shared__ float sm[];
    float* Qs = sm;                   // [64][64]  Qs[r][d], pre-scaled by 1/8
    float* Kt = Qs + 64 * 64;         // [64][66]  Kt[d][t]
    float* Vs = Kt + 64 * 66;         // [64][66]  Vs[t][c]
    float* Ps = Vs + 64 * 66;         // [64][66]  Ps[r][t] (per-warp private rows)

    const int h    = blockIdx.y;
    const int q0   = blockIdx.x * 64;
    const int tid  = threadIdx.x;
    const int warp = tid >> 5;
    const int lane = tid & 31;
    const int r0   = warp * 8;
    const int tc0  = lane * 2;

    const float* qb = g_qh + (size_t)h * S_LEN * HDIM;
    const float* kb = g_kh + (size_t)h * S_LEN * HDIM;
    const float* vb = g_vh + (size_t)h * S_LEN * HDIM;

    for (int i = tid; i < 64 * 64; i += 256)
        Qs[i] = qb[(size_t)(q0 + (i >> 6)) * HDIM + (i & 63)] * 0.125f;

    float m_r[8], l_r[8], o0[8], o1[8];
#pragma unroll
    for (int r = 0; r < 8; r++) {
        m_r[r] = -1e30f; l_r[r] = 0.0f; o0[r] = 0.0f; o1[r] = 0.0f;
    }

    for (int kt = 0; kt < S_LEN; kt += 64) {
        __syncthreads();   // prior iteration's Kt/Vs reads complete (also guards Qs on iter 0)
#pragma unroll 4
        for (int i = tid; i < 64 * 64; i += 256) {
            const int t = i >> 6, d = i & 63;
            const float* krow = kb + (size_t)(kt + t) * HDIM;
            const float* vrow = vb + (size_t)(kt + t) * HDIM;
            Kt[d * 66 + t] = krow[d];
            Vs[t * 66 + d] = vrow[d];
        }
        __syncthreads();

        // ---- scores: s[r][tc0], s[r][tc0+1] = (Q*scale) . K ----
        float s0[8], s1[8];
#pragma unroll
        for (int r = 0; r < 8; r++) { s0[r] = 0.0f; s1[r] = 0.0f; }
#pragma unroll 4
        for (int d = 0; d < 64; d++) {
            const float2 kk = *(const float2*)&Kt[d * 66 + tc0];
#pragma unroll
            for (int r = 0; r < 8; r++) {
                const float qv = Qs[(r0 + r) * 64 + d];   // warp broadcast
                s0[r] = fmaf(qv, kk.x, s0[r]);
                s1[r] = fmaf(qv, kk.y, s1[r]);
            }
        }

        // ---- online softmax per row (full-warp reductions) ----
#pragma unroll
        for (int r = 0; r < 8; r++) {
            float mx = fmaxf(s0[r], s1[r]);
#pragma unroll
            for (int off = 16; off > 0; off >>= 1)
                mx = fmaxf(mx, __shfl_xor_sync(0xffffffffu, mx, off));
            const float mnew  = fmaxf(m_r[r], mx);
            const float alpha = __expf(m_r[r] - mnew);
            const float p0 = __expf(s0[r] - mnew);
            const float p1 = __expf(s1[r] - mnew);
            float ps = p0 + p1;
#pragma unroll
            for (int off = 16; off > 0; off >>= 1)
                ps += __shfl_xor_sync(0xffffffffu, ps, off);
            l_r[r] = l_r[r] * alpha + ps;
            m_r[r] = mnew;
            o0[r] *= alpha; o1[r] *= alpha;
            *(float2*)&Ps[(r0 + r) * 66 + tc0] = make_float2(p0, p1);
        }
        __syncwarp();   // Ps rows are per-warp private; warp-local visibility suffices

        // ---- O += P @ V (process t in pairs) ----
#pragma unroll 4
        for (int t = 0; t < 64; t += 2) {
            const float2 va = *(const float2*)&Vs[t * 66 + tc0];
            const float2 vb2 = *(const float2*)&Vs[(t + 1) * 66 + tc0];
#pragma unroll
            for (int r = 0; r < 8; r++) {
                const float2 pp = *(const float2*)&Ps[(r0 + r) * 66 + t];  // broadcast
                o0[r] = fmaf(pp.x, va.x,  o0[r]);
                o1[r] = fmaf(pp.x, va.y,  o1[r]);
                o0[r] = fmaf(pp.y, vb2.x, o0[r]);
                o1[r] = fmaf(pp.y, vb2.y, o1[r]);
            }
        }
    }

#pragma unroll
    for (int r = 0; r < 8; r++) {
        const float inv = 1.0f / l_r[r];
        const size_t row = (size_t)(q0 + r0 + r);
        *(float2*)&g_attn[row * DMODEL + h * HDIM + tc0] =
            make_float2(o0[r] * inv, o1[r] * inv);
    }
}

// ---------------------------------------------------------------------------

static const int ATTN_SMEM = (64 * 64 + 3 * 64 * 66) * (int)sizeof(float);  // 67072 B

extern "C" void kernel_launch(void* const* d_in, const int* in_sizes, int n_in,
                              void* d_out, int out_size) {
    const float* q  = (const float*)d_in[0];
    const float* k  = (const float*)d_in[1];
    const float* v  = (const float*)d_in[2];
    const float* Wq = (const float*)d_in[3];
    const float* bq = (const float*)d_in[4];
    const float* Wk = (const float*)d_in[5];
    const float* bk = (const float*)d_in[6];
    const float* Wv = (const float*)d_in[7];
    const float* bv = (const float*)d_in[8];
    const float* Wo = (const float*)d_in[9];
    const float* bo = (const float*)d_in[10];
    float* out = (float*)d_out;

    float *qh, *kh, *vh, *attn;
    cudaGetSymbolAddress((void**)&qh,   g_qh);
    cudaGetSymbolAddress((void**)&kh,   g_kh);
    cudaGetSymbolAddress((void**)&vh,   g_vh);
    cudaGetSymbolAddress((void**)&attn, g_attn);

    cudaFuncSetAttribute(attn_kernel,
                         cudaFuncAttributeMaxDynamicSharedMemorySize, ATTN_SMEM);

    const dim3 gg(DMODEL / 128, S_LEN / 128);   // (6, 32)

    gemm_bias_kernel<<<gg, 256>>>(q, Wq, bq, qh, 1);
    gemm_bias_kernel<<<gg, 256>>>(k, Wk, bk, kh, 1);
    gemm_bias_kernel<<<gg, 256>>>(v, Wv, bv, vh, 1);
    attn_kernel<<<dim3(S_LEN / 64, NHEAD), 256, ATTN_SMEM>>>();
    gemm_bias_kernel<<<gg, 256>>>(attn, Wo, bo, out, 0);
}

// round 2
// speedup vs baseline: 3.5949x; 3.5949x over previous
#include <cuda_runtime.h>
#include <math.h>
#include <stdint.h>

#define S_LEN   4096
#define DMODEL  768
#define NHEAD   12
#define HDIM    64

// Scratch (allocation-free per harness rules)
__device__ float g_qh[NHEAD * S_LEN * HDIM];   // [H][S][Hd]
__device__ float g_kh[NHEAD * S_LEN * HDIM];
__device__ float g_vh[NHEAD * S_LEN * HDIM];
__device__ float g_attn[S_LEN * DMODEL];       // [S][H*Hd]

// ---------------------------------------------------------------------------
// helpers
// ---------------------------------------------------------------------------
__device__ __forceinline__ uint32_t f2tf32(float x) {
    uint32_t r;
    asm("cvt.rna.tf32.f32 %0, %1;" : "=r"(r) : "f"(x));
    return r;
}
__device__ __forceinline__ float tf32f(float x) {
    return __uint_as_float(f2tf32(x));
}

__device__ __forceinline__ void mma_tf32(float c[4],
                                         uint32_t a0, uint32_t a1, uint32_t a2, uint32_t a3,
                                         uint32_t b0, uint32_t b1) {
    asm volatile(
        "mma.sync.aligned.m16n8k8.row.col.f32.tf32.tf32.f32 "
        "{%0,%1,%2,%3}, {%4,%5,%6,%7}, {%8,%9}, {%0,%1,%2,%3};\n"
        : "+f"(c[0]), "+f"(c[1]), "+f"(c[2]), "+f"(c[3])
        : "r"(a0), "r"(a1), "r"(a2), "r"(a3), "r"(b0), "r"(b1));
}

// ---------------------------------------------------------------------------
// GEMM: C = A(4096x768) @ W^T + bias, tf32 tensor cores.
// Block tile 128x128, BK=32, 8 warps (4m x 2n), warp tile 32x64.
// headMajor=1: C[(n>>6)][m][(n&63)], headMajor=0: C[m][n]
// ---------------------------------------------------------------------------
#define GSTRIDE 36

__global__ __launch_bounds__(256, 2)
void gemm_tf32_kernel(const float* __restrict__ A, const float* __restrict__ W,
                      const float* __restrict__ bias, float* __restrict__ C,
                      int headMajor) {
    __shared__ float As[128 * GSTRIDE];
    __shared__ float Ws[128 * GSTRIDE];

    const int tid  = threadIdx.x;
    const int warp = tid >> 5;
    const int lane = tid & 31;
    const int g    = lane >> 2;     // 0..7
    const int t    = lane & 3;      // 0..3
    const int m0   = blockIdx.y * 128;
    const int n0b  = blockIdx.x * 128;
    const int wm   = (warp >> 1) * 32;   // 0,32,64,96
    const int wn   = (warp & 1) * 64;    // 0,64

    float acc[2][8][4];
#pragma unroll
    for (int s = 0; s < 2; s++)
#pragma unroll
        for (int n = 0; n < 8; n++)
#pragma unroll
            for (int i = 0; i < 4; i++) acc[s][n][i] = 0.0f;

    for (int k0 = 0; k0 < DMODEL; k0 += 32) {
        __syncthreads();
#pragma unroll
        for (int i = 0; i < 4; i++) {
            const int seg = tid + i * 256;
            const int r = seg >> 3;
            const int c = (seg & 7) * 4;
            float4 av = *(const float4*)(A + (size_t)(m0 + r) * DMODEL + k0 + c);
            float4 wv = *(const float4*)(W + (size_t)(n0b + r) * DMODEL + k0 + c);
            av.x = tf32f(av.x); av.y = tf32f(av.y); av.z = tf32f(av.z); av.w = tf32f(av.w);
            wv.x = tf32f(wv.x); wv.y = tf32f(wv.y); wv.z = tf32f(wv.z); wv.w = tf32f(wv.w);
            *(float4*)&As[r * GSTRIDE + c] = av;
            *(float4*)&Ws[r * GSTRIDE + c] = wv;
        }
        __syncthreads();

#pragma unroll
        for (int s = 0; s < 4; s++) {          // k8 steps within BK=32
            uint32_t a[2][4];
#pragma unroll
            for (int sub = 0; sub < 2; sub++) {
                const int row = wm + sub * 16;
                a[sub][0] = __float_as_uint(As[(row + g)     * GSTRIDE + s * 8 + t]);
                a[sub][1] = __float_as_uint(As[(row + g + 8) * GSTRIDE + s * 8 + t]);
                a[sub][2] = __float_as_uint(As[(row + g)     * GSTRIDE + s * 8 + t + 4]);
                a[sub][3] = __float_as_uint(As[(row + g + 8) * GSTRIDE + s * 8 + t + 4]);
            }
#pragma unroll
            for (int nt = 0; nt < 8; nt++) {
                const uint32_t b0 = __float_as_uint(Ws[(wn + nt * 8 + g) * GSTRIDE + s * 8 + t]);
                const uint32_t b1 = __float_as_uint(Ws[(wn + nt * 8 + g) * GSTRIDE + s * 8 + t + 4]);
                mma_tf32(acc[0][nt], a[0][0], a[0][1], a[0][2], a[0][3], b0, b1);
                mma_tf32(acc[1][nt], a[1][0], a[1][1], a[1][2], a[1][3], b0, b1);
            }
        }
    }

    // epilogue
#pragma unroll
    for (int sub = 0; sub < 2; sub++) {
#pragma unroll
        for (int nt = 0; nt < 8; nt++) {
            const int r1 = m0 + wm + sub * 16 + g;
            const int r2 = r1 + 8;
            const int c0 = n0b + wn + nt * 8 + 2 * t;
            const float b0v = bias[c0], b1v = bias[c0 + 1];
            const float2 v0 = make_float2(acc[sub][nt][0] + b0v, acc[sub][nt][1] + b1v);
            const float2 v1 = make_float2(acc[sub][nt][2] + b0v, acc[sub][nt][3] + b1v);
            if (headMajor) {
                const size_t base = (size_t)(c0 >> 6) * S_LEN;
                *(float2*)&C[(base + r1) * HDIM + (c0 & 63)] = v0;
                *(float2*)&C[(base + r2) * HDIM + (c0 & 63)] = v1;
            } else {
                *(float2*)&C[(size_t)r1 * DMODEL + c0] = v0;
                *(float2*)&C[(size_t)r2 * DMODEL + c0] = v1;
            }
        }
    }
}

// ---------------------------------------------------------------------------
// Flash attention, tf32 tensor cores.
// Block = (head, 128-row Q tile), 256 threads = 8 warps, warp owns 16 rows.
// Q fragments register-resident; K,V staged row-major [t][d]; P via smem.
// ---------------------------------------------------------------------------
#define KSTRIDE 68
#define VSTRIDE 72
#define PSTRIDE 68

// smem floats: Ps 128*68 (also Q staging) + Ks 64*68 + Vs 64*72
#define ATTN_SMEM_FLOATS (128 * PSTRIDE + 64 * KSTRIDE + 64 * VSTRIDE)

__global__ __launch_bounds__(256, 2)
void attn_kernel() {
    extern __shared__ float sm[];
    float* Ps = sm;                         // [128][68] (Q staging then P)
    float* Ks = Ps + 128 * PSTRIDE;         // [64][68]
    float* Vs = Ks + 64 * KSTRIDE;          // [64][72]

    const int h    = blockIdx.y;
    const int q0   = blockIdx.x * 128;
    const int tid  = threadIdx.x;
    const int warp = tid >> 5;
    const int lane = tid & 31;
    const int g    = lane >> 2;
    const int t    = lane & 3;
    const int wrow = warp * 16;

    const float* qb = g_qh + (size_t)h * S_LEN * HDIM;
    const float* kb = g_kh + (size_t)h * S_LEN * HDIM;
    const float* vb = g_vh + (size_t)h * S_LEN * HDIM;

    // stage Q (scaled by 1/8, tf32) into Ps region
#pragma unroll
    for (int i = tid; i < 128 * 16; i += 256) {
        const int r = i >> 4, c4 = (i & 15) * 4;
        float4 qv = *(const float4*)(qb + (size_t)(q0 + r) * HDIM + c4);
        qv.x = tf32f(qv.x * 0.125f); qv.y = tf32f(qv.y * 0.125f);
        qv.z = tf32f(qv.z * 0.125f); qv.w = tf32f(qv.w * 0.125f);
        *(float4*)&Ps[r * PSTRIDE + c4] = qv;
    }
    __syncthreads();

    // Q fragments: 8 k-steps x 4 regs, register-resident for whole loop
    uint32_t qf[8][4];
#pragma unroll
    for (int s = 0; s < 8; s++) {
        qf[s][0] = __float_as_uint(Ps[(wrow + g)     * PSTRIDE + s * 8 + t]);
        qf[s][1] = __float_as_uint(Ps[(wrow + g + 8) * PSTRIDE + s * 8 + t]);
        qf[s][2] = __float_as_uint(Ps[(wrow + g)     * PSTRIDE + s * 8 + t + 4]);
        qf[s][3] = __float_as_uint(Ps[(wrow + g + 8) * PSTRIDE + s * 8 + t + 4]);
    }
    // (Ps rows wrow..wrow+16 are private to this warp from here on)

    float of[8][4];
#pragma unroll
    for (int n = 0; n < 8; n++)
#pragma unroll
        for (int i = 0; i < 4; i++) of[n][i] = 0.0f;
    float m1 = -1e30f, m2 = -1e30f, l1 = 0.0f, l2 = 0.0f;

    for (int kt = 0; kt < S_LEN; kt += 64) {
        __syncthreads();   // previous iteration's K/V reads complete
#pragma unroll
        for (int i = tid; i < 64 * 16; i += 256) {
            const int r = i >> 4, c4 = (i & 15) * 4;
            float4 kv = *(const float4*)(kb + (size_t)(kt + r) * HDIM + c4);
            float4 vv = *(const float4*)(vb + (size_t)(kt + r) * HDIM + c4);
            kv.x = tf32f(kv.x); kv.y = tf32f(kv.y); kv.z = tf32f(kv.z); kv.w = tf32f(kv.w);
            vv.x = tf32f(vv.x); vv.y = tf32f(vv.y); vv.z = tf32f(vv.z); vv.w = tf32f(vv.w);
            *(float4*)&Ks[r * KSTRIDE + c4] = kv;
            *(float4*)&Vs[r * VSTRIDE + c4] = vv;
        }
        __syncthreads();

        // ---- S = (Q*scale) @ K^T : m16 x n64 per warp ----
        float sf[8][4];
#pragma unroll
        for (int n = 0; n < 8; n++)
#pragma unroll
            for (int i = 0; i < 4; i++) sf[n][i] = 0.0f;

#pragma unroll
        for (int s = 0; s < 8; s++) {
#pragma unroll
            for (int nt = 0; nt < 8; nt++) {
                const uint32_t b0 = __float_as_uint(Ks[(nt * 8 + g) * KSTRIDE + s * 8 + t]);
                const uint32_t b1 = __float_as_uint(Ks[(nt * 8 + g) * KSTRIDE + s * 8 + t + 4]);
                mma_tf32(sf[nt], qf[s][0], qf[s][1], qf[s][2], qf[s][3], b0, b1);
            }
        }

        // ---- online softmax (rows g and g+8 of this warp's 16) ----
        float mx1 = -1e30f, mx2 = -1e30f;
#pragma unroll
        for (int nt = 0; nt < 8; nt++) {
            mx1 = fmaxf(mx1, fmaxf(sf[nt][0], sf[nt][1]));
            mx2 = fmaxf(mx2, fmaxf(sf[nt][2], sf[nt][3]));
        }
#pragma unroll
        for (int off = 1; off <= 2; off <<= 1) {
            mx1 = fmaxf(mx1, __shfl_xor_sync(0xffffffffu, mx1, off));
            mx2 = fmaxf(mx2, __shfl_xor_sync(0xffffffffu, mx2, off));
        }
        const float M1 = fmaxf(m1, mx1);
        const float M2 = fmaxf(m2, mx2);
        const float al1 = __expf(m1 - M1);
        const float al2 = __expf(m2 - M2);
        float s1 = 0.0f, s2 = 0.0f;
#pragma unroll
        for (int nt = 0; nt < 8; nt++) {
            const float p0 = __expf(sf[nt][0] - M1);
            const float p1 = __expf(sf[nt][1] - M1);
            const float p2 = __expf(sf[nt][2] - M2);
            const float p3 = __expf(sf[nt][3] - M2);
            s1 += p0 + p1;
            s2 += p2 + p3;
            const int col = nt * 8 + 2 * t;
            *(float2*)&Ps[(wrow + g)     * PSTRIDE + col] =
                make_float2(__uint_as_float(f2tf32(p0)), __uint_as_float(f2tf32(p1)));
            *(float2*)&Ps[(wrow + g + 8) * PSTRIDE + col] =
                make_float2(__uint_as_float(f2tf32(p2)), __uint_as_float(f2tf32(p3)));
            of[nt][0] *= al1; of[nt][1] *= al1;
            of[nt][2] *= al2; of[nt][3] *= al2;
        }
#pragma unroll
        for (int off = 1; off <= 2; off <<= 1) {
            s1 += __shfl_xor_sync(0xffffffffu, s1, off);
            s2 += __shfl_xor_sync(0xffffffffu, s2, off);
        }
        l1 = l1 * al1 + s1;
        l2 = l2 * al2 + s2;
        m1 = M1; m2 = M2;
        __syncwarp();

        // ---- O += P @ V ----
#pragma unroll
        for (int s = 0; s < 8; s++) {        // k-steps over t-dim
            const uint32_t a0 = __float_as_uint(Ps[(wrow + g)     * PSTRIDE + s * 8 + t]);
            const uint32_t a1 = __float_as_uint(Ps[(wrow + g + 8) * PSTRIDE + s * 8 + t]);
            const uint32_t a2 = __float_as_uint(Ps[(wrow + g)     * PSTRIDE + s * 8 + t + 4]);
            const uint32_t a3 = __float_as_uint(Ps[(wrow + g + 8) * PSTRIDE + s * 8 + t + 4]);
#pragma unroll
            for (int nt = 0; nt < 8; nt++) {
                const uint32_t b0 = __float_as_uint(Vs[(s * 8 + t)     * VSTRIDE + nt * 8 + g]);
                const uint32_t b1 = __float_as_uint(Vs[(s * 8 + t + 4) * VSTRIDE + nt * 8 + g]);
                mma_tf32(of[nt], a0, a1, a2, a3, b0, b1);
            }
        }
        __syncwarp();   // Ps reads done before next iteration's overwrite
    }

    // ---- normalize + write ----
    const float inv1 = 1.0f / l1;
    const float inv2 = 1.0f / l2;
#pragma unroll
    for (int nt = 0; nt < 8; nt++) {
        const int col = h * HDIM + nt * 8 + 2 * t;
        const size_t r1 = (size_t)(q0 + wrow + g);
        const size_t r2 = r1 + 8;
        *(float2*)&g_attn[r1 * DMODEL + col] =
            make_float2(of[nt][0] * inv1, of[nt][1] * inv1);
        *(float2*)&g_attn[r2 * DMODEL + col] =
            make_float2(of[nt][2] * inv2, of[nt][3] * inv2);
    }
}

// ---------------------------------------------------------------------------

static const int ATTN_SMEM = ATTN_SMEM_FLOATS * (int)sizeof(float);

extern "C" void kernel_launch(void* const* d_in, const int* in_sizes, int n_in,
                              void* d_out, int out_size) {
    const float* q  = (const float*)d_in[0];
    const float* k  = (const float*)d_in[1];
    const float* v  = (const float*)d_in[2];
    const float* Wq = (const float*)d_in[3];
    const float* bq = (const float*)d_in[4];
    const float* Wk = (const float*)d_in[5];
    const float* bk = (const float*)d_in[6];
    const float* Wv = (const float*)d_in[7];
    const float* bv = (const float*)d_in[8];
    const float* Wo = (const float*)d_in[9];
    const float* bo = (const float*)d_in[10];
    float* out = (float*)d_out;

    float *qh, *kh, *vh, *attn;
    cudaGetSymbolAddress((void**)&qh,   g_qh);
    cudaGetSymbolAddress((void**)&kh,   g_kh);
    cudaGetSymbolAddress((void**)&vh,   g_vh);
    cudaGetSymbolAddress((void**)&attn, g_attn);

    cudaFuncSetAttribute(attn_kernel,
                         cudaFuncAttributeMaxDynamicSharedMemorySize, ATTN_SMEM);

    const dim3 gg(DMODEL / 128, S_LEN / 128);   // (6, 32)

    gemm_tf32_kernel<<<gg, 256>>>(q, Wq, bq, qh, 1);
    gemm_tf32_kernel<<<gg, 256>>>(k, Wk, bk, kh, 1);
    gemm_tf32_kernel<<<gg, 256>>>(v, Wv, bv, vh, 1);
    attn_kernel<<<dim3(S_LEN / 128, NHEAD), 256, ATTN_SMEM>>>();
    gemm_tf32_kernel<<<gg, 256>>>(attn, Wo, bo, out, 0);
}